// round 8
// baseline (speedup 1.0000x reference)
#include <cuda_runtime.h>
#include <cuda_bf16.h>
#include <math_constants.h>
#include <cstdint>

#define BB   8
#define CCH  192
#define OUTC 384
#define NN   3136            // H*W = 56*56
#define KNB  16
#define MTOT (BB*NN)         // 25088
#define NT64 (NN/64)         // 49 tiles per dim
#define NPAIR ((NT64*(NT64+1))/2)   // 1225 upper-tri tile pairs
#define MB64 (MTOT/64)       // 392
#define QCAP 512             // per-warp candidate queue capacity
#define FULLM 0xffffffffu
#define KC   576             // concatenated split-bf16 K (3 x 192)
#define KC16 (KC/16)         // 36 k-steps
#define DELTA 0.05f          // threshold margin >> mma approx error

typedef unsigned long long u64;

// packed f32x2 helpers (sm_100a)
__device__ __forceinline__ u64 pack2(float x, float y) {
    u64 r; asm("mov.b64 %0, {%1, %2};" : "=l"(r) : "f"(x), "f"(y)); return r;
}
__device__ __forceinline__ void unpack2(u64 p, float& x, float& y) {
    asm("mov.b64 {%0, %1}, %2;" : "=f"(x), "=f"(y) : "l"(p));
}
__device__ __forceinline__ void fma2(u64& d, u64 a, u64 b) {
    asm("fma.rn.f32x2 %0, %1, %2, %0;" : "+l"(d) : "l"(a), "l"(b));
}

// mma helpers
__device__ __forceinline__ void mma16816(float* c, const unsigned* a, const unsigned* b) {
    asm volatile("mma.sync.aligned.m16n8k16.row.col.f32.bf16.bf16.f32 "
                 "{%0,%1,%2,%3}, {%4,%5,%6,%7}, {%8,%9}, {%0,%1,%2,%3};"
                 : "+f"(c[0]), "+f"(c[1]), "+f"(c[2]), "+f"(c[3])
                 : "r"(a[0]), "r"(a[1]), "r"(a[2]), "r"(a[3]), "r"(b[0]), "r"(b[1]));
}
__device__ __forceinline__ void ldsm4(unsigned* d, unsigned addr) {
    asm volatile("ldmatrix.sync.aligned.m8n8.x4.shared.b16 {%0,%1,%2,%3}, [%4];"
                 : "=r"(d[0]), "=r"(d[1]), "=r"(d[2]), "=r"(d[3]) : "r"(addr));
}
__device__ __forceinline__ void ldsm2(unsigned* d, unsigned addr) {
    asm volatile("ldmatrix.sync.aligned.m8n8.x2.shared.b16 {%0,%1}, [%2];"
                 : "=r"(d[0]), "=r"(d[1]) : "r"(addr));
}

// ---------------- device scratch (no allocs allowed) ----------------
__device__ float g_xt[(size_t)BB*NN*CCH];          // (B,N,C) fp32 features
__device__ float g_x2[BB*NN];                      // row squared norms
__device__ uint4 g_ca4[(size_t)BB*NN*KC/8];        // bf16 [h|h|l] rows (16B units)
__device__ uint4 g_cb4[(size_t)BB*NN*KC/8];        // bf16 [h|l|h] rows
__device__ float g_dist[(size_t)BB*NN*NN];         // 315 MB approx distance matrix
__device__ int   g_idx[(size_t)BB*NN*KNB];         // top-K neighbor indices
__device__ float g_feat[(size_t)BB*NN*2*CCH];      // interleaved (x, maxrel)
__device__ float g_y[(size_t)BB*NN*OUTC];          // pre-BN conv output
__device__ float g_psum[MB64*OUTC];                // BN partial sums
__device__ float g_psq[MB64*OUTC];                 // BN partial sumsq
__device__ float g_scale[OUTC];
__device__ float g_shift[OUTC];

// ---------------- 1) transpose x (B,C,N) -> xt (B,N,C) + bf16 split ----------------
__global__ void k_transpose(const float* __restrict__ x) {
    __shared__ float tile[32][33];
    int b  = blockIdx.z;
    int n0 = blockIdx.x * 32, c0 = blockIdx.y * 32;
    int tx = threadIdx.x, ty = threadIdx.y;
    tile[ty][tx] = x[((size_t)b*CCH + c0 + ty)*NN + n0 + tx];
    __syncthreads();
    float xv = tile[tx][ty];
    g_xt[((size_t)b*NN + n0 + ty)*CCH + c0 + tx] = xv;
    __nv_bfloat16 h = __float2bfloat16(xv);
    __nv_bfloat16 l = __float2bfloat16(xv - __bfloat162float(h));
    __nv_bfloat16* ca = (__nv_bfloat16*)g_ca4;
    __nv_bfloat16* cb = (__nv_bfloat16*)g_cb4;
    size_t base = (size_t)(b*NN + n0 + ty)*KC + c0 + tx;
    ca[base] = h;  ca[base + 192] = h;  ca[base + 384] = l;
    cb[base] = h;  cb[base + 192] = l;  cb[base + 384] = h;
}

// ---------------- 2) row squared norms ----------------
__global__ void k_x2() {
    int row  = blockIdx.x * 8 + (threadIdx.x >> 5);
    int lane = threadIdx.x & 31;
    const float* p = g_xt + (size_t)row * CCH;
    float s = 0.f;
    for (int c = lane; c < CCH; c += 32) { float v = p[c]; s += v * v; }
    #pragma unroll
    for (int o = 16; o; o >>= 1) s += __shfl_down_sync(FULLM, s, o);
    if (lane == 0) g_x2[row] = s;
}

// ---------------- 3) distance via split-bf16 tensor-core GEMM ----------------
// 64x64 tile, 4 warps (each 32x32), K=576 concat: h.h + h.l + l.h.
__global__ void k_dist() {
    int b = blockIdx.y;
    int p = blockIdx.x;
    int ti = 0, rem = p;
    while (rem >= NT64 - ti) { rem -= NT64 - ti; ti++; }
    int tj = ti + rem;
    int i0 = ti * 64, j0 = tj * 64;

    // 48B row stride -> conflict-free ldmatrix
    __shared__ __align__(16) __nv_bfloat16 As[64*24];
    __shared__ __align__(16) __nv_bfloat16 Bs[64*24];
    __shared__ float Ts[64][65];

    int tid = threadIdx.x;
    int w = tid >> 5, lane = tid & 31;
    int wm = (w >> 1) * 32, wn = (w & 1) * 32;

    float acc[2][4][4];
    #pragma unroll
    for (int mf = 0; mf < 2; mf++)
        #pragma unroll
        for (int nf = 0; nf < 4; nf++)
            #pragma unroll
            for (int e = 0; e < 4; e++) acc[mf][nf][e] = 0.f;

    const uint4* pa = g_ca4 + (size_t)b * NN * (KC/8);
    const uint4* pb = g_cb4 + (size_t)b * NN * (KC/8);
    int lrow = tid >> 1, lhalf = tid & 1;

    unsigned asb = (unsigned)__cvta_generic_to_shared(As);
    unsigned bsb = (unsigned)__cvta_generic_to_shared(Bs);
    // ldmatrix source addresses (fixed per thread)
    unsigned aAddr0 = asb + (wm      + (lane & 15)) * 48 + ((lane >> 4) << 4);
    unsigned aAddr1 = asb + (wm + 16 + (lane & 15)) * 48 + ((lane >> 4) << 4);
    unsigned bAddrB = bsb + (wn + (lane & 7)) * 48 + (((lane >> 3) & 1) << 4);

    for (int s = 0; s < KC16; s++) {
        uint4 va = pa[(size_t)(i0 + lrow) * (KC/8) + 2*s + lhalf];
        uint4 vb = pb[(size_t)(j0 + lrow) * (KC/8) + 2*s + lhalf];
        *(uint4*)(As + lrow*24 + lhalf*8) = va;
        *(uint4*)(Bs + lrow*24 + lhalf*8) = vb;
        __syncthreads();

        unsigned afr[2][4], bfr[4][2];
        ldsm4(afr[0], aAddr0);
        ldsm4(afr[1], aAddr1);
        #pragma unroll
        for (int nf = 0; nf < 4; nf++) ldsm2(bfr[nf], bAddrB + nf*8*48);
        #pragma unroll
        for (int mf = 0; mf < 2; mf++)
            #pragma unroll
            for (int nf = 0; nf < 4; nf++)
                mma16816(acc[mf][nf], afr[mf], bfr[nf]);
        __syncthreads();
    }

    // epilogue: d = x2i + x2j - 2*inner
    int qr = lane >> 2, qc = (lane & 3) * 2;
    float rx2[2][2], cx2[4][2];
    #pragma unroll
    for (int mf = 0; mf < 2; mf++) {
        rx2[mf][0] = g_x2[b*NN + i0 + wm + mf*16 + qr];
        rx2[mf][1] = g_x2[b*NN + i0 + wm + mf*16 + qr + 8];
    }
    #pragma unroll
    for (int nf = 0; nf < 4; nf++) {
        cx2[nf][0] = g_x2[b*NN + j0 + wn + nf*8 + qc];
        cx2[nf][1] = g_x2[b*NN + j0 + wn + nf*8 + qc + 1];
    }
    #pragma unroll
    for (int mf = 0; mf < 2; mf++) {
        #pragma unroll
        for (int nf = 0; nf < 4; nf++) {
            int r0 = wm + mf*16 + qr, r1 = r0 + 8;
            int cc = wn + nf*8 + qc;
            float d00 = rx2[mf][0] + cx2[nf][0] - 2.f*acc[mf][nf][0];
            float d01 = rx2[mf][0] + cx2[nf][1] - 2.f*acc[mf][nf][1];
            float d10 = rx2[mf][1] + cx2[nf][0] - 2.f*acc[mf][nf][2];
            float d11 = rx2[mf][1] + cx2[nf][1] - 2.f*acc[mf][nf][3];
            *(float2*)&g_dist[((size_t)b*NN + i0 + r0)*NN + j0 + cc] = make_float2(d00, d01);
            *(float2*)&g_dist[((size_t)b*NN + i0 + r1)*NN + j0 + cc] = make_float2(d10, d11);
            Ts[cc][r0] = d00; Ts[cc+1][r0] = d01;
            Ts[cc][r1] = d10; Ts[cc+1][r1] = d11;
        }
    }
    if (ti != tj) {
        __syncthreads();
        #pragma unroll
        for (int e = 0; e < 32; e++) {
            int q = tid + e * 128;
            int r = q >> 6, cc = q & 63;
            g_dist[((size_t)b*NN + j0 + r)*NN + i0 + cc] = Ts[r][cc];
        }
    }
}

// ---------------- 4) top-K: threshold select on approx + exact fp32 rescore ----------------
__global__ void k_topk() {
    __shared__ float qv[8][QCAP];
    __shared__ int   qi[8][QCAP];
    int w = threadIdx.x >> 5, lane = threadIdx.x & 31;
    int row = blockIdx.x * 8 + w;
    const float4* dr4 = (const float4*)(g_dist + (size_t)row * NN);
    unsigned lmask_lt = (1u << lane) - 1u;

    // ---- Pass 1: per-lane two smallest (approx values) ----
    float a0 = CUDART_INF_F, a1 = CUDART_INF_F;
    const int NQ = NN / 4;            // 784 quads
    for (int i = 0; i < (NQ + 31) / 32; i++) {
        int q = i * 32 + lane;
        if (q < NQ) {
            float4 v = dr4[q];
            float m01 = fminf(v.x, v.y), m23 = fminf(v.z, v.w);
            float mq = fminf(m01, m23);
            if (mq < a1) {
                #pragma unroll
                for (int c = 0; c < 4; c++) {
                    float d = (c == 0) ? v.x : (c == 1) ? v.y : (c == 2) ? v.z : v.w;
                    if (d < a1) { if (d < a0) { a1 = a0; a0 = d; } else a1 = d; }
                }
            }
        }
    }

    // ---- pop 16 smallest -> tau16, then add safety margin ----
    float h0 = a0, h1 = a1;
    float tau = CUDART_INF_F;
    int popped = 0;
    #pragma unroll 1
    for (int it = 0; it < KNB && popped < KNB; it++) {
        float m = h0;
        #pragma unroll
        for (int o = 16; o; o >>= 1) m = fminf(m, __shfl_down_sync(FULLM, m, o));
        m = __shfl_sync(FULLM, m, 0);
        unsigned hit = __ballot_sync(FULLM, h0 == m);
        popped += __popc(hit);
        tau = m;
        if (h0 == m) { h0 = h1; h1 = CUDART_INF_F; }
    }
    tau += DELTA;   // margin >> split-bf16 approx error: true top-16 all pass

    // ---- Pass 2: compact candidates (d_approx <= tau) ----
    float* myqv = qv[w];
    int*   myqi = qi[w];
    int cnt = 0;
    for (int i = 0; i < (NQ + 31) / 32; i++) {
        int q = i * 32 + lane;
        bool valid = q < NQ;
        float4 v = valid ? dr4[q] : make_float4(CUDART_INF_F, CUDART_INF_F, CUDART_INF_F, CUDART_INF_F);
        float mq = fminf(fminf(v.x, v.y), fminf(v.z, v.w));
        unsigned anyb = __ballot_sync(FULLM, mq <= tau);
        if (anyb == 0) continue;
        #pragma unroll
        for (int c = 0; c < 4; c++) {
            float d = (c == 0) ? v.x : (c == 1) ? v.y : (c == 2) ? v.z : v.w;
            bool h = d <= tau;
            unsigned bm = __ballot_sync(FULLM, h);
            if (h) {
                int pos = cnt + __popc(bm & lmask_lt);
                if (pos < QCAP) { myqv[pos] = d; myqi[pos] = q * 4 + c; }
            }
            cnt += __popc(bm);
        }
    }
    if (cnt > QCAP) cnt = QCAP;
    __syncwarp();

    // ---- Pass 3: exact fp32 rescore of candidates (same order as k_x2) ----
    {
        int b = row / NN;
        const float* xrow = g_xt + (size_t)row * CCH;
        const float* xb = g_xt + (size_t)b * NN * CCH;
        float xr[6];
        #pragma unroll
        for (int c = 0; c < 6; c++) xr[c] = xrow[lane + 32*c];
        float myx2 = g_x2[row];
        for (int p = 0; p < cnt; p++) {
            int j = myqi[p];
            const float* xj = xb + (size_t)j * CCH;
            float s = 0.f;
            #pragma unroll
            for (int c = 0; c < 6; c++) s += xr[c] * xj[lane + 32*c];
            #pragma unroll
            for (int o = 16; o; o >>= 1) s += __shfl_down_sync(FULLM, s, o);
            if (lane == 0) myqv[p] = myx2 + g_x2[b*NN + j] - 2.f * s;
        }
        __syncwarp();
    }

    // ---- exact selection: 16 rounds of lexicographic argmin over queue ----
    float bv = CUDART_INF_F; int bi = 0x7fffffff, bp = -1;
    for (int p = lane; p < cnt; p += 32) {
        float v = myqv[p]; int ix = myqi[p];
        if (v < bv || (v == bv && ix < bi)) { bv = v; bi = ix; bp = p; }
    }
    for (int k = 0; k < KNB; k++) {
        float rv = bv; int ri = bi, rp = bp, rl = lane;
        #pragma unroll
        for (int o = 16; o; o >>= 1) {
            float ov = __shfl_down_sync(FULLM, rv, o);
            int   oi = __shfl_down_sync(FULLM, ri, o);
            int   op = __shfl_down_sync(FULLM, rp, o);
            int   ol = __shfl_down_sync(FULLM, rl, o);
            if (ov < rv || (ov == rv && oi < ri)) { rv = ov; ri = oi; rp = op; rl = ol; }
        }
        int wi = __shfl_sync(FULLM, ri, 0);
        int wp = __shfl_sync(FULLM, rp, 0);
        int wl = __shfl_sync(FULLM, rl, 0);
        if (lane == 0) g_idx[(size_t)row * KNB + k] = wi;
        if (lane == wl) {
            myqv[wp] = CUDART_INF_F;
            bv = CUDART_INF_F; bi = 0x7fffffff; bp = -1;
            for (int p = lane; p < cnt; p += 32) {
                float v = myqv[p]; int ix = myqi[p];
                if (v < bv || (v == bv && ix < bi)) { bv = v; bi = ix; bp = p; }
            }
        }
        __syncwarp();
    }
}

// ---------------- 5) gather + max-relative + interleaved feat ----------------
__global__ void k_feat() {
    __shared__ int ji[KNB];
    int m = blockIdx.x;          // b*N + n
    int c = threadIdx.x;         // 192 threads
    if (c < KNB) ji[c] = g_idx[(size_t)m*KNB + c];
    __syncthreads();
    int b = m / NN;
    const float* xb = g_xt + (size_t)b * NN * CCH;
    float xc = g_xt[(size_t)m*CCH + c];
    float mx = -CUDART_INF_F;
    #pragma unroll
    for (int k = 0; k < KNB; k++) {
        float v = xb[(size_t)ji[k]*CCH + c];
        mx = fmaxf(mx, v - xc);
    }
    float2 o; o.x = xc; o.y = mx;
    *(float2*)&g_feat[(size_t)m*(2*CCH) + 2*c] = o;
}

// ---------------- 6) y = feat @ w^T + bias (f32x2 packed FMA) ----------------
__global__ void k_gemm2(const float* __restrict__ w, const float* __restrict__ bias) {
    int m0 = blockIdx.x * 64;
    int o0 = blockIdx.y * 64;
    __shared__ __align__(16) float As[16][64];
    __shared__ __align__(16) float Bs[16][64];
    int tid = threadIdx.x;
    int tx = tid & 15, ty = tid >> 4;

    u64 accp[4][4];
    #pragma unroll
    for (int i = 0; i < 4; i++)
        #pragma unroll
        for (int c = 0; c < 4; c++) accp[i][c] = 0ull;

    for (int kk = 0; kk < 2*CCH; kk += 16) {
        #pragma unroll
        for (int e = 0; e < 2; e++) {
            int q = tid + e * 128;
            int m = q >> 2, k4 = (q & 3) << 2;
            float4 va = *(const float4*)(g_feat + (size_t)(m0 + m)*(2*CCH) + kk + k4);
            As[k4+0][m] = va.x; As[k4+1][m] = va.y; As[k4+2][m] = va.z; As[k4+3][m] = va.w;
            float4 vb = *(const float4*)(w + (size_t)(o0 + m)*(2*CCH) + kk + k4);
            Bs[k4+0][m] = vb.x; Bs[k4+1][m] = vb.y; Bs[k4+2][m] = vb.z; Bs[k4+3][m] = vb.w;
        }
        __syncthreads();
        #pragma unroll
        for (int k = 0; k < 16; k++) {
            u64 a01[4];
            #pragma unroll
            for (int i = 0; i < 4; i++)
                a01[i] = *(const u64*)&As[k][ty*8 + 2*i];
            float4 bq = *(const float4*)&Bs[k][tx*4];
            u64 bb[4] = { pack2(bq.x, bq.x), pack2(bq.y, bq.y),
                          pack2(bq.z, bq.z), pack2(bq.w, bq.w) };
            #pragma unroll
            for (int i = 0; i < 4; i++)
                #pragma unroll
                for (int c = 0; c < 4; c++) fma2(accp[i][c], a01[i], bb[c]);
        }
        __syncthreads();
    }

    float acc[8][4];
    #pragma unroll
    for (int i = 0; i < 4; i++)
        #pragma unroll
        for (int c = 0; c < 4; c++)
            unpack2(accp[i][c], acc[2*i][c], acc[2*i+1][c]);

    #pragma unroll
    for (int r = 0; r < 8; r++) {
        #pragma unroll
        for (int c = 0; c < 4; c++) {
            int o = o0 + tx*4 + c;
            g_y[(size_t)(m0 + ty*8 + r)*OUTC + o] = acc[r][c] + bias[o];
        }
    }
}

// ---------------- 7) BN partial sums (deterministic, no atomics) ----------------
__global__ void k_bnpart() {
    int o  = threadIdx.x;        // 384 threads
    int m0 = blockIdx.x * 64;    // 392 blocks
    float s = 0.f, q = 0.f;
    for (int r = 0; r < 64; r++) {
        float v = g_y[(size_t)(m0 + r)*OUTC + o];
        s += v; q += v * v;
    }
    g_psum[blockIdx.x*OUTC + o] = s;
    g_psq [blockIdx.x*OUTC + o] = q;
}

// ---------------- 8) BN finalize -> scale/shift ----------------
__global__ void k_bnfin(const float* __restrict__ gamma, const float* __restrict__ beta) {
    __shared__ float ss[256], sq[256];
    int o = blockIdx.x, t = threadIdx.x;
    float s = 0.f, q = 0.f;
    for (int p = t; p < MB64; p += 256) { s += g_psum[p*OUTC + o]; q += g_psq[p*OUTC + o]; }
    ss[t] = s; sq[t] = q; __syncthreads();
    for (int st = 128; st; st >>= 1) {
        if (t < st) { ss[t] += ss[t+st]; sq[t] += sq[t+st]; }
        __syncthreads();
    }
    if (t == 0) {
        float mean = ss[0] / (float)MTOT;
        float var  = sq[0] / (float)MTOT - mean*mean;
        float rs   = rsqrtf(var + 1e-5f);
        float sc   = gamma[o] * rs;
        g_scale[o] = sc;
        g_shift[o] = beta[o] - mean * sc;
    }
}

// ---------------- 9) normalize + ReLU + transpose to (B,OUT,N) ----------------
__global__ void k_out(float* __restrict__ out) {
    __shared__ float tile[32][33];
    int b  = blockIdx.z;
    int n0 = blockIdx.x * 32, o0 = blockIdx.y * 32;
    int tx = threadIdx.x, ty = threadIdx.y;
    int o = o0 + tx;
    float v = g_y[(size_t)(b*NN + n0 + ty)*OUTC + o];
    v = v * g_scale[o] + g_shift[o];
    tile[ty][tx] = fmaxf(v, 0.f);
    __syncthreads();
    out[((size_t)b*OUTC + o0 + ty)*NN + n0 + tx] = tile[tx][ty];
}

// ---------------- launch ----------------
extern "C" void kernel_launch(void* const* d_in, const int* in_sizes, int n_in,
                              void* d_out, int out_size) {
    const float* x     = (const float*)d_in[0];
    const float* w     = (const float*)d_in[1];
    const float* bias  = (const float*)d_in[2];
    const float* gamma = (const float*)d_in[3];
    const float* beta  = (const float*)d_in[4];
    float* out = (float*)d_out;

    dim3 tposeGrid(NN/32, CCH/32, BB);
    k_transpose<<<tposeGrid, dim3(32,32)>>>(x);
    k_x2<<<MTOT/8, 256>>>();
    k_dist<<<dim3(NPAIR, BB), 128>>>();
    k_topk<<<MTOT/8, 256>>>();
    k_feat<<<MTOT, CCH>>>();
    k_gemm2<<<dim3(MTOT/64, OUTC/64), 128>>>(w, bias);
    k_bnpart<<<MB64, OUTC>>>();
    k_bnfin<<<OUTC, 256>>>(gamma, beta);
    k_out<<<dim3(NN/32, OUTC/32, BB), dim3(32,32)>>>(out);
}

// round 11
// speedup vs baseline: 1.3444x; 1.3444x over previous
#include <cuda_runtime.h>
#include <cuda_bf16.h>
#include <math_constants.h>
#include <cstdint>

#define BB   8
#define CCH  192
#define OUTC 384
#define NN   3136            // H*W = 56*56
#define KNB  16
#define MTOT (BB*NN)         // 25088
#define NT64 (NN/64)         // 49 tiles per dim
#define NPAIR ((NT64*(NT64+1))/2)   // 1225 upper-tri tile pairs
#define MB64 (MTOT/64)       // 392
#define QCAP 512             // per-warp candidate queue capacity
#define FULLM 0xffffffffu
#define KC   576             // concatenated split-bf16 K (3 x 192)
#define KSTG 64              // K columns per pipeline stage (128 B/row)
#define NSTG (KC/KSTG)       // 9 stages
#define SSTR 144             // smem row stride in BYTES (128+16 -> conflict-free ldmatrix)
#define DELTA 3.0f           // margin: covers bf16 dist quantization + mma error

typedef unsigned long long u64;

// packed f32x2 helpers (sm_100a)
__device__ __forceinline__ u64 pack2(float x, float y) {
    u64 r; asm("mov.b64 %0, {%1, %2};" : "=l"(r) : "f"(x), "f"(y)); return r;
}
__device__ __forceinline__ void unpack2(u64 p, float& x, float& y) {
    asm("mov.b64 {%0, %1}, %2;" : "=f"(x), "=f"(y) : "l"(p));
}
__device__ __forceinline__ void fma2(u64& d, u64 a, u64 b) {
    asm("fma.rn.f32x2 %0, %1, %2, %0;" : "+l"(d) : "l"(a), "l"(b));
}

// mma / ldmatrix / cp.async helpers
__device__ __forceinline__ void mma16816(float* c, const unsigned* a, const unsigned* b) {
    asm volatile("mma.sync.aligned.m16n8k16.row.col.f32.bf16.bf16.f32 "
                 "{%0,%1,%2,%3}, {%4,%5,%6,%7}, {%8,%9}, {%0,%1,%2,%3};"
                 : "+f"(c[0]), "+f"(c[1]), "+f"(c[2]), "+f"(c[3])
                 : "r"(a[0]), "r"(a[1]), "r"(a[2]), "r"(a[3]), "r"(b[0]), "r"(b[1]));
}
__device__ __forceinline__ void ldsm4(unsigned* d, unsigned addr) {
    asm volatile("ldmatrix.sync.aligned.m8n8.x4.shared.b16 {%0,%1,%2,%3}, [%4];"
                 : "=r"(d[0]), "=r"(d[1]), "=r"(d[2]), "=r"(d[3]) : "r"(addr));
}
__device__ __forceinline__ void ldsm2(unsigned* d, unsigned addr) {
    asm volatile("ldmatrix.sync.aligned.m8n8.x2.shared.b16 {%0,%1}, [%2];"
                 : "=r"(d[0]), "=r"(d[1]) : "r"(addr));
}
__device__ __forceinline__ void cpasync16(unsigned smem, const void* g) {
    asm volatile("cp.async.cg.shared.global [%0], [%1], 16;" :: "r"(smem), "l"(g));
}
__device__ __forceinline__ void cp_commit() { asm volatile("cp.async.commit_group;"); }

// ---------------- device scratch (no allocs allowed) ----------------
__device__ float g_xt[(size_t)BB*NN*CCH];          // (B,N,C) fp32 features
__device__ float g_x2[BB*NN];                      // row squared norms
__device__ uint4 g_ca4[(size_t)BB*NN*KC/8];        // bf16 [h|h|l] rows (16B units)
__device__ uint4 g_cb4[(size_t)BB*NN*KC/8];        // bf16 [h|l|h] rows
__device__ __nv_bfloat16 g_dist[(size_t)BB*NN*NN]; // 157 MB approx distance matrix
__device__ int   g_idx[(size_t)BB*NN*KNB];         // top-K neighbor indices
__device__ float g_feat[(size_t)BB*NN*2*CCH];      // interleaved (x, maxrel)
__device__ float g_y[(size_t)BB*NN*OUTC];          // pre-BN conv output
__device__ float g_psum[MB64*OUTC];                // BN partial sums
__device__ float g_psq[MB64*OUTC];                 // BN partial sumsq
__device__ float g_scale[OUTC];
__device__ float g_shift[OUTC];

// ---------------- 1) transpose x (B,C,N) -> xt (B,N,C) + bf16 split ----------------
__global__ void k_transpose(const float* __restrict__ x) {
    __shared__ float tile[32][33];
    int b  = blockIdx.z;
    int n0 = blockIdx.x * 32, c0 = blockIdx.y * 32;
    int tx = threadIdx.x, ty = threadIdx.y;
    tile[ty][tx] = x[((size_t)b*CCH + c0 + ty)*NN + n0 + tx];
    __syncthreads();
    float xv = tile[tx][ty];
    g_xt[((size_t)b*NN + n0 + ty)*CCH + c0 + tx] = xv;
    __nv_bfloat16 h = __float2bfloat16(xv);
    __nv_bfloat16 l = __float2bfloat16(xv - __bfloat162float(h));
    __nv_bfloat16* ca = (__nv_bfloat16*)g_ca4;
    __nv_bfloat16* cb = (__nv_bfloat16*)g_cb4;
    size_t base = (size_t)(b*NN + n0 + ty)*KC + c0 + tx;
    ca[base] = h;  ca[base + 192] = h;  ca[base + 384] = l;
    cb[base] = h;  cb[base + 192] = l;  cb[base + 384] = h;
}

// ---------------- 2) row squared norms ----------------
__global__ void k_x2() {
    int row  = blockIdx.x * 8 + (threadIdx.x >> 5);
    int lane = threadIdx.x & 31;
    const float* p = g_xt + (size_t)row * CCH;
    float s = 0.f;
    for (int c = lane; c < CCH; c += 32) { float v = p[c]; s += v * v; }
    #pragma unroll
    for (int o = 16; o; o >>= 1) s += __shfl_down_sync(FULLM, s, o);
    if (lane == 0) g_x2[row] = s;
}

// ---------------- 3) distance: split-bf16 mma, cp.async double-buffered ----------------
// Stage = 64 K-cols (128 B/row, 144 B stride). smem: 4*64*144 + Ts = 45312 B < 48 KB.
__global__ void k_dist() {
    int b = blockIdx.y;
    int p = blockIdx.x;
    int ti = 0, rem = p;
    while (rem >= NT64 - ti) { rem -= NT64 - ti; ti++; }
    int tj = ti + rem;
    int i0 = ti * 64, j0 = tj * 64;

    __shared__ __align__(16) char As[2][64*SSTR];
    __shared__ __align__(16) char Bs[2][64*SSTR];
    __shared__ __nv_bfloat16 Ts[64][66];

    int tid = threadIdx.x;
    int w = tid >> 5, lane = tid & 31;
    int wm = (w >> 1) * 32, wn = (w & 1) * 32;

    float acc[2][4][4];
    #pragma unroll
    for (int mf = 0; mf < 2; mf++)
        #pragma unroll
        for (int nf = 0; nf < 4; nf++)
            #pragma unroll
            for (int e = 0; e < 4; e++) acc[mf][nf][e] = 0.f;

    const char* gA = (const char*)g_ca4 + (size_t)b * NN * (KC*2);
    const char* gB = (const char*)g_cb4 + (size_t)b * NN * (KC*2);
    unsigned sA[2] = { (unsigned)__cvta_generic_to_shared(As[0]),
                       (unsigned)__cvta_generic_to_shared(As[1]) };
    unsigned sB[2] = { (unsigned)__cvta_generic_to_shared(Bs[0]),
                       (unsigned)__cvta_generic_to_shared(Bs[1]) };

    // issue one stage: 64 rows x 128 B per operand, 16 B chunks (512/operand; 4 iters)
    #define ISSUE(s) do {                                                     \
        int _buf = (s) & 1;                                                   \
        _Pragma("unroll")                                                     \
        for (int _e = 0; _e < 4; _e++) {                                      \
            int _q = tid + _e * 128;                                          \
            int _row = _q >> 3, _c16 = _q & 7;                                \
            cpasync16(sA[_buf] + _row*SSTR + _c16*16,                         \
                      gA + (size_t)(i0 + _row)*(KC*2) + (s)*128 + _c16*16);   \
            cpasync16(sB[_buf] + _row*SSTR + _c16*16,                         \
                      gB + (size_t)(j0 + _row)*(KC*2) + (s)*128 + _c16*16);   \
        }                                                                     \
        cp_commit();                                                          \
    } while (0)

    ISSUE(0);
    for (int s = 0; s < NSTG; s++) {
        if (s + 1 < NSTG) {
            ISSUE(s + 1);
            asm volatile("cp.async.wait_group 1;");
        } else {
            asm volatile("cp.async.wait_group 0;");
        }
        __syncthreads();
        int buf = s & 1;
        unsigned ab = sA[buf], bbs = sB[buf];
        unsigned aA0 = ab + (wm      + (lane & 15)) * SSTR + ((lane >> 4) << 4);
        unsigned aA1 = ab + (wm + 16 + (lane & 15)) * SSTR + ((lane >> 4) << 4);
        unsigned bA  = bbs + (wn + (lane & 7)) * SSTR + (((lane >> 3) & 1) << 4);
        #pragma unroll
        for (int kf = 0; kf < KSTG/16; kf++) {
            unsigned afr[2][4], bfr[4][2];
            ldsm4(afr[0], aA0 + kf*32);
            ldsm4(afr[1], aA1 + kf*32);
            #pragma unroll
            for (int nf = 0; nf < 4; nf++) ldsm2(bfr[nf], bA + nf*8*SSTR + kf*32);
            #pragma unroll
            for (int mf = 0; mf < 2; mf++)
                #pragma unroll
                for (int nf = 0; nf < 4; nf++)
                    mma16816(acc[mf][nf], afr[mf], bfr[nf]);
        }
        __syncthreads();
    }
    #undef ISSUE

    // epilogue: d = x2i + x2j - 2*inner, store bf16 (direct + transposed tile)
    int qr = lane >> 2, qc = (lane & 3) * 2;
    float rx2[2][2], cx2[4][2];
    #pragma unroll
    for (int mf = 0; mf < 2; mf++) {
        rx2[mf][0] = g_x2[b*NN + i0 + wm + mf*16 + qr];
        rx2[mf][1] = g_x2[b*NN + i0 + wm + mf*16 + qr + 8];
    }
    #pragma unroll
    for (int nf = 0; nf < 4; nf++) {
        cx2[nf][0] = g_x2[b*NN + j0 + wn + nf*8 + qc];
        cx2[nf][1] = g_x2[b*NN + j0 + wn + nf*8 + qc + 1];
    }
    #pragma unroll
    for (int mf = 0; mf < 2; mf++) {
        #pragma unroll
        for (int nf = 0; nf < 4; nf++) {
            int r0 = wm + mf*16 + qr, r1 = r0 + 8;
            int cc = wn + nf*8 + qc;
            __nv_bfloat16 d00 = __float2bfloat16(rx2[mf][0] + cx2[nf][0] - 2.f*acc[mf][nf][0]);
            __nv_bfloat16 d01 = __float2bfloat16(rx2[mf][0] + cx2[nf][1] - 2.f*acc[mf][nf][1]);
            __nv_bfloat16 d10 = __float2bfloat16(rx2[mf][1] + cx2[nf][0] - 2.f*acc[mf][nf][2]);
            __nv_bfloat16 d11 = __float2bfloat16(rx2[mf][1] + cx2[nf][1] - 2.f*acc[mf][nf][3]);
            __nv_bfloat162 p0; p0.x = d00; p0.y = d01;
            __nv_bfloat162 p1; p1.x = d10; p1.y = d11;
            *(__nv_bfloat162*)&g_dist[((size_t)b*NN + i0 + r0)*NN + j0 + cc] = p0;
            *(__nv_bfloat162*)&g_dist[((size_t)b*NN + i0 + r1)*NN + j0 + cc] = p1;
            Ts[cc][r0] = d00; Ts[cc+1][r0] = d01;
            Ts[cc][r1] = d10; Ts[cc+1][r1] = d11;
        }
    }
    if (ti != tj) {
        __syncthreads();
        #pragma unroll
        for (int e = 0; e < 16; e++) {
            int q = tid + e * 128;          // 2048 = 64 rows x 32 pairs
            int r = q >> 5, c2 = (q & 31) * 2;
            __nv_bfloat162 pv; pv.x = Ts[r][c2]; pv.y = Ts[r][c2+1];
            *(__nv_bfloat162*)&g_dist[((size_t)b*NN + j0 + r)*NN + i0 + c2] = pv;
        }
    }
}

// ---------------- 4) top-K: threshold select on bf16 approx + exact fp32 rescore ----------------
__global__ void k_topk() {
    __shared__ float qv[8][QCAP];
    __shared__ int   qi[8][QCAP];
    int w = threadIdx.x >> 5, lane = threadIdx.x & 31;
    int row = blockIdx.x * 8 + w;
    const uint4* dr8 = (const uint4*)(g_dist + (size_t)row * NN);
    unsigned lmask_lt = (1u << lane) - 1u;
    const int NC8 = NN / 8;           // 392 chunks of 8 bf16

    // ---- Pass 1: per-lane two smallest ----
    float a0 = CUDART_INF_F, a1 = CUDART_INF_F;
    for (int i = 0; i < (NC8 + 31) / 32; i++) {
        int q = i * 32 + lane;
        if (q < NC8) {
            uint4 v = dr8[q];
            float2 f0 = __bfloat1622float2(*(__nv_bfloat162*)&v.x);
            float2 f1 = __bfloat1622float2(*(__nv_bfloat162*)&v.y);
            float2 f2 = __bfloat1622float2(*(__nv_bfloat162*)&v.z);
            float2 f3 = __bfloat1622float2(*(__nv_bfloat162*)&v.w);
            float d[8] = {f0.x, f0.y, f1.x, f1.y, f2.x, f2.y, f3.x, f3.y};
            float mn = d[0];
            #pragma unroll
            for (int c = 1; c < 8; c++) mn = fminf(mn, d[c]);
            if (mn < a1) {
                #pragma unroll
                for (int c = 0; c < 8; c++) {
                    float dd = d[c];
                    if (dd < a1) { if (dd < a0) { a1 = a0; a0 = dd; } else a1 = dd; }
                }
            }
        }
    }

    // ---- pop 16 smallest -> tau, add safety margin ----
    float h0 = a0, h1 = a1;
    float tau = CUDART_INF_F;
    int popped = 0;
    #pragma unroll 1
    for (int it = 0; it < KNB && popped < KNB; it++) {
        float m = h0;
        #pragma unroll
        for (int o = 16; o; o >>= 1) m = fminf(m, __shfl_down_sync(FULLM, m, o));
        m = __shfl_sync(FULLM, m, 0);
        unsigned hit = __ballot_sync(FULLM, h0 == m);
        popped += __popc(hit);
        tau = m;
        if (h0 == m) { h0 = h1; h1 = CUDART_INF_F; }
    }
    tau += DELTA;

    // ---- Pass 2: compact candidates (bf16 approx <= tau) ----
    float* myqv = qv[w];
    int*   myqi = qi[w];
    int cnt = 0;
    for (int i = 0; i < (NC8 + 31) / 32; i++) {
        int q = i * 32 + lane;
        bool valid = q < NC8;
        float d[8];
        if (valid) {
            uint4 v = dr8[q];
            float2 f0 = __bfloat1622float2(*(__nv_bfloat162*)&v.x);
            float2 f1 = __bfloat1622float2(*(__nv_bfloat162*)&v.y);
            float2 f2 = __bfloat1622float2(*(__nv_bfloat162*)&v.z);
            float2 f3 = __bfloat1622float2(*(__nv_bfloat162*)&v.w);
            d[0]=f0.x; d[1]=f0.y; d[2]=f1.x; d[3]=f1.y; d[4]=f2.x; d[5]=f2.y; d[6]=f3.x; d[7]=f3.y;
        } else {
            #pragma unroll
            for (int c = 0; c < 8; c++) d[c] = CUDART_INF_F;
        }
        float mn = d[0];
        #pragma unroll
        for (int c = 1; c < 8; c++) mn = fminf(mn, d[c]);
        unsigned anyb = __ballot_sync(FULLM, mn <= tau);
        if (anyb == 0) continue;
        #pragma unroll
        for (int c = 0; c < 8; c++) {
            bool h = d[c] <= tau;
            unsigned bm = __ballot_sync(FULLM, h);
            if (h) {
                int pos = cnt + __popc(bm & lmask_lt);
                if (pos < QCAP) { myqv[pos] = d[c]; myqi[pos] = q * 8 + c; }
            }
            cnt += __popc(bm);
        }
    }
    if (cnt > QCAP) cnt = QCAP;
    __syncwarp();

    // ---- Pass 3: exact fp32 rescore (same reduction order as k_x2) ----
    {
        int b = row / NN;
        const float* xrow = g_xt + (size_t)row * CCH;
        const float* xb = g_xt + (size_t)b * NN * CCH;
        float xr[6];
        #pragma unroll
        for (int c = 0; c < 6; c++) xr[c] = xrow[lane + 32*c];
        float myx2 = g_x2[row];
        for (int p = 0; p < cnt; p++) {
            int j = myqi[p];
            const float* xj = xb + (size_t)j * CCH;
            float s = 0.f;
            #pragma unroll
            for (int c = 0; c < 6; c++) s += xr[c] * xj[lane + 32*c];
            #pragma unroll
            for (int o = 16; o; o >>= 1) s += __shfl_down_sync(FULLM, s, o);
            if (lane == 0) myqv[p] = myx2 + g_x2[b*NN + j] - 2.f * s;
        }
        __syncwarp();
    }

    // ---- exact selection: 16 rounds of lexicographic argmin ----
    float bv = CUDART_INF_F; int bi = 0x7fffffff, bp = -1;
    for (int p = lane; p < cnt; p += 32) {
        float v = myqv[p]; int ix = myqi[p];
        if (v < bv || (v == bv && ix < bi)) { bv = v; bi = ix; bp = p; }
    }
    for (int k = 0; k < KNB; k++) {
        float rv = bv; int ri = bi, rp = bp, rl = lane;
        #pragma unroll
        for (int o = 16; o; o >>= 1) {
            float ov = __shfl_down_sync(FULLM, rv, o);
            int   oi = __shfl_down_sync(FULLM, ri, o);
            int   op = __shfl_down_sync(FULLM, rp, o);
            int   ol = __shfl_down_sync(FULLM, rl, o);
            if (ov < rv || (ov == rv && oi < ri)) { rv = ov; ri = oi; rp = op; rl = ol; }
        }
        int wi = __shfl_sync(FULLM, ri, 0);
        int wp = __shfl_sync(FULLM, rp, 0);
        int wl = __shfl_sync(FULLM, rl, 0);
        if (lane == 0) g_idx[(size_t)row * KNB + k] = wi;
        if (lane == wl) {
            myqv[wp] = CUDART_INF_F;
            bv = CUDART_INF_F; bi = 0x7fffffff; bp = -1;
            for (int p = lane; p < cnt; p += 32) {
                float v = myqv[p]; int ix = myqi[p];
                if (v < bv || (v == bv && ix < bi)) { bv = v; bi = ix; bp = p; }
            }
        }
        __syncwarp();
    }
}

// ---------------- 5) gather + max-relative + interleaved feat ----------------
__global__ void k_feat() {
    __shared__ int ji[KNB];
    int m = blockIdx.x;          // b*N + n
    int c = threadIdx.x;         // 192 threads
    if (c < KNB) ji[c] = g_idx[(size_t)m*KNB + c];
    __syncthreads();
    int b = m / NN;
    const float* xb = g_xt + (size_t)b * NN * CCH;
    float xc = g_xt[(size_t)m*CCH + c];
    float mx = -CUDART_INF_F;
    #pragma unroll
    for (int k = 0; k < KNB; k++) {
        float v = xb[(size_t)ji[k]*CCH + c];
        mx = fmaxf(mx, v - xc);
    }
    float2 o; o.x = xc; o.y = mx;
    *(float2*)&g_feat[(size_t)m*(2*CCH) + 2*c] = o;
}

// ---------------- 6) y = feat @ w^T + bias (f32x2 packed FMA) ----------------
__global__ void k_gemm2(const float* __restrict__ w, const float* __restrict__ bias) {
    int m0 = blockIdx.x * 64;
    int o0 = blockIdx.y * 64;
    __shared__ __align__(16) float As[16][64];
    __shared__ __align__(16) float Bs[16][64];
    int tid = threadIdx.x;
    int tx = tid & 15, ty = tid >> 4;

    u64 accp[4][4];
    #pragma unroll
    for (int i = 0; i < 4; i++)
        #pragma unroll
        for (int c = 0; c < 4; c++) accp[i][c] = 0ull;

    for (int kk = 0; kk < 2*CCH; kk += 16) {
        #pragma unroll
        for (int e = 0; e < 2; e++) {
            int q = tid + e * 128;
            int m = q >> 2, k4 = (q & 3) << 2;
            float4 va = *(const float4*)(g_feat + (size_t)(m0 + m)*(2*CCH) + kk + k4);
            As[k4+0][m] = va.x; As[k4+1][m] = va.y; As[k4+2][m] = va.z; As[k4+3][m] = va.w;
            float4 vb = *(const float4*)(w + (size_t)(o0 + m)*(2*CCH) + kk + k4);
            Bs[k4+0][m] = vb.x; Bs[k4+1][m] = vb.y; Bs[k4+2][m] = vb.z; Bs[k4+3][m] = vb.w;
        }
        __syncthreads();
        #pragma unroll
        for (int k = 0; k < 16; k++) {
            u64 a01[4];
            #pragma unroll
            for (int i = 0; i < 4; i++)
                a01[i] = *(const u64*)&As[k][ty*8 + 2*i];
            float4 bq = *(const float4*)&Bs[k][tx*4];
            u64 bb[4] = { pack2(bq.x, bq.x), pack2(bq.y, bq.y),
                          pack2(bq.z, bq.z), pack2(bq.w, bq.w) };
            #pragma unroll
            for (int i = 0; i < 4; i++)
                #pragma unroll
                for (int c = 0; c < 4; c++) fma2(accp[i][c], a01[i], bb[c]);
        }
        __syncthreads();
    }

    float acc[8][4];
    #pragma unroll
    for (int i = 0; i < 4; i++)
        #pragma unroll
        for (int c = 0; c < 4; c++)
            unpack2(accp[i][c], acc[2*i][c], acc[2*i+1][c]);

    #pragma unroll
    for (int r = 0; r < 8; r++) {
        #pragma unroll
        for (int c = 0; c < 4; c++) {
            int o = o0 + tx*4 + c;
            g_y[(size_t)(m0 + ty*8 + r)*OUTC + o] = acc[r][c] + bias[o];
        }
    }
}

// ---------------- 7) BN partial sums (deterministic, no atomics) ----------------
__global__ void k_bnpart() {
    int o  = threadIdx.x;        // 384 threads
    int m0 = blockIdx.x * 64;    // 392 blocks
    float s = 0.f, q = 0.f;
    for (int r = 0; r < 64; r++) {
        float v = g_y[(size_t)(m0 + r)*OUTC + o];
        s += v; q += v * v;
    }
    g_psum[blockIdx.x*OUTC + o] = s;
    g_psq [blockIdx.x*OUTC + o] = q;
}

// ---------------- 8) BN finalize -> scale/shift ----------------
__global__ void k_bnfin(const float* __restrict__ gamma, const float* __restrict__ beta) {
    __shared__ float ss[256], sq[256];
    int o = blockIdx.x, t = threadIdx.x;
    float s = 0.f, q = 0.f;
    for (int p = t; p < MB64; p += 256) { s += g_psum[p*OUTC + o]; q += g_psq[p*OUTC + o]; }
    ss[t] = s; sq[t] = q; __syncthreads();
    for (int st = 128; st; st >>= 1) {
        if (t < st) { ss[t] += ss[t+st]; sq[t] += sq[t+st]; }
        __syncthreads();
    }
    if (t == 0) {
        float mean = ss[0] / (float)MTOT;
        float var  = sq[0] / (float)MTOT - mean*mean;
        float rs   = rsqrtf(var + 1e-5f);
        float sc   = gamma[o] * rs;
        g_scale[o] = sc;
        g_shift[o] = beta[o] - mean * sc;
    }
}

// ---------------- 9) normalize + ReLU + transpose to (B,OUT,N) ----------------
__global__ void k_out(float* __restrict__ out) {
    __shared__ float tile[32][33];
    int b  = blockIdx.z;
    int n0 = blockIdx.x * 32, o0 = blockIdx.y * 32;
    int tx = threadIdx.x, ty = threadIdx.y;
    int o = o0 + tx;
    float v = g_y[(size_t)(b*NN + n0 + ty)*OUTC + o];
    v = v * g_scale[o] + g_shift[o];
    tile[ty][tx] = fmaxf(v, 0.f);
    __syncthreads();
    out[((size_t)b*OUTC + o0 + ty)*NN + n0 + tx] = tile[tx][ty];
}

// ---------------- launch ----------------
extern "C" void kernel_launch(void* const* d_in, const int* in_sizes, int n_in,
                              void* d_out, int out_size) {
    const float* x     = (const float*)d_in[0];
    const float* w     = (const float*)d_in[1];
    const float* bias  = (const float*)d_in[2];
    const float* gamma = (const float*)d_in[3];
    const float* beta  = (const float*)d_in[4];
    float* out = (float*)d_out;

    dim3 tposeGrid(NN/32, CCH/32, BB);
    k_transpose<<<tposeGrid, dim3(32,32)>>>(x);
    k_x2<<<MTOT/8, 256>>>();
    k_dist<<<dim3(NPAIR, BB), 128>>>();
    k_topk<<<MTOT/8, 256>>>();
    k_feat<<<MTOT, CCH>>>();
    k_gemm2<<<dim3(MTOT/64, OUTC/64), 128>>>(w, bias);
    k_bnpart<<<MB64, OUTC>>>();
    k_bnfin<<<OUTC, 256>>>(gamma, beta);
    k_out<<<dim3(NN/32, OUTC/32, BB), dim3(32,32)>>>(out);
}